// round 1
// baseline (speedup 1.0000x reference)
#include <cuda_runtime.h>
#include <math.h>

// Problem constants
constexpr int Bc = 4;
constexpr int Sc = 4096;
constexpr int Dc = 1024;
constexpr int Hc = 16;
constexpr int HDc = 64;
constexpr int Wc = 128;
constexpr int NWIN = Bc * (Sc / Wc);   // 128 windows total
constexpr int Mrows = Bc * Sc;         // 16384

// Scratch (device globals: allocation-free rule)
__device__ float g_Q[Bc * Sc * Dc];
__device__ float g_K[Bc * Sc * Dc];
__device__ float g_V[Bc * Sc * Dc];
__device__ float g_O[Bc * Sc * Dc];
__device__ float g_GO[Bc * 32 * Dc];

// ---------------------------------------------------------------------------
// GEMM: Y[m,n] = sum_k X[m,k] * Wt[n,k] + bias[n]
// X: (M,K) row-major, Wt: (N,K) row-major. BM=BN=128, BK=16, 256 threads, 8x8.
// ---------------------------------------------------------------------------
__global__ __launch_bounds__(256) void gemm_bias_kernel(
    const float* __restrict__ X, const float* __restrict__ Wt,
    const float* __restrict__ bias, float* __restrict__ Y,
    int M, int N, int K)
{
    constexpr int BM = 128, BN = 128, BK = 16;
    __shared__ __align__(16) float As[BK][BM + 4];
    __shared__ __align__(16) float Bs[BK][BN + 4];

    const int tid = threadIdx.x;
    const int tx = tid & 15;       // 0..15 -> n
    const int ty = tid >> 4;       // 0..15 -> m
    const int m0 = blockIdx.y * BM;
    const int n0 = blockIdx.x * BN;

    float acc[8][8];
#pragma unroll
    for (int i = 0; i < 8; i++)
#pragma unroll
        for (int j = 0; j < 8; j++) acc[i][j] = 0.f;

    for (int k0 = 0; k0 < K; k0 += BK) {
#pragma unroll
        for (int l = 0; l < 2; l++) {
            int f = tid + l * 256;          // 0..511
            int row = f >> 2;               // 0..127
            int c4 = (f & 3) * 4;           // 0,4,8,12
            float4 va = *(const float4*)(X + (size_t)(m0 + row) * K + k0 + c4);
            As[c4 + 0][row] = va.x; As[c4 + 1][row] = va.y;
            As[c4 + 2][row] = va.z; As[c4 + 3][row] = va.w;
            float4 vb = *(const float4*)(Wt + (size_t)(n0 + row) * K + k0 + c4);
            Bs[c4 + 0][row] = vb.x; Bs[c4 + 1][row] = vb.y;
            Bs[c4 + 2][row] = vb.z; Bs[c4 + 3][row] = vb.w;
        }
        __syncthreads();

#pragma unroll
        for (int kk = 0; kk < BK; kk++) {
            float a[8], b[8];
            *(float4*)(a + 0) = *(const float4*)&As[kk][ty * 8 + 0];
            *(float4*)(a + 4) = *(const float4*)&As[kk][ty * 8 + 4];
            *(float4*)(b + 0) = *(const float4*)&Bs[kk][tx * 8 + 0];
            *(float4*)(b + 4) = *(const float4*)&Bs[kk][tx * 8 + 4];
#pragma unroll
            for (int i = 0; i < 8; i++)
#pragma unroll
                for (int j = 0; j < 8; j++) acc[i][j] += a[i] * b[j];
        }
        __syncthreads();
    }

    // epilogue with bias
    float bv[8];
#pragma unroll
    for (int j = 0; j < 8; j++) bv[j] = bias[n0 + tx * 8 + j];
#pragma unroll
    for (int i = 0; i < 8; i++) {
        int row = m0 + ty * 8 + i;
        float* yp = Y + (size_t)row * N + n0 + tx * 8;
        float4 o0, o1;
        o0.x = acc[i][0] + bv[0]; o0.y = acc[i][1] + bv[1];
        o0.z = acc[i][2] + bv[2]; o0.w = acc[i][3] + bv[3];
        o1.x = acc[i][4] + bv[4]; o1.y = acc[i][5] + bv[5];
        o1.z = acc[i][6] + bv[6]; o1.w = acc[i][7] + bv[7];
        *(float4*)(yp + 0) = o0;
        *(float4*)(yp + 4) = o1;
    }
}

// ---------------------------------------------------------------------------
// Windowed attention: grid (NWIN, H), 128 threads; thread = one query row.
// K/V tile staged in dynamic smem (64 KB); online softmax in registers.
// ---------------------------------------------------------------------------
__global__ __launch_bounds__(128) void window_attn_kernel(
    const float* __restrict__ Qp, const float* __restrict__ Kp,
    const float* __restrict__ Vp, float* __restrict__ Op)
{
    extern __shared__ __align__(16) float sm[];
    float* Ks = sm;                 // [128][64]
    float* Vs = sm + Wc * HDc;      // [128][64]

    const int win = blockIdx.x;
    const int h = blockIdx.y;
    const size_t base = (size_t)win * Wc * Dc;
    const int tid = threadIdx.x;

    for (int idx = tid; idx < Wc * HDc; idx += 128) {
        int r = idx >> 6, c = idx & 63;
        size_t g = base + (size_t)r * Dc + h * HDc + c;
        Ks[idx] = Kp[g];
        Vs[idx] = Vp[g];
    }
    __syncthreads();

    const int r = tid;
    float4 q[16];
    const float4* qg = (const float4*)(Qp + base + (size_t)r * Dc + h * HDc);
#pragma unroll
    for (int i = 0; i < 16; i++) q[i] = qg[i];

    float mx = -1e30f, l = 0.f;
    float4 acc[16];
#pragma unroll
    for (int i = 0; i < 16; i++) acc[i] = make_float4(0.f, 0.f, 0.f, 0.f);

    const float4* K4 = (const float4*)Ks;
    const float4* V4 = (const float4*)Vs;

    for (int k = 0; k < Wc; k++) {
        float s0 = 0.f, s1 = 0.f, s2 = 0.f, s3 = 0.f;
#pragma unroll
        for (int i = 0; i < 16; i++) {
            float4 kv = K4[k * 16 + i];
            s0 += q[i].x * kv.x;
            s1 += q[i].y * kv.y;
            s2 += q[i].z * kv.z;
            s3 += q[i].w * kv.w;
        }
        float s = (s0 + s1 + s2 + s3) * 0.125f;   // 1/sqrt(64)
        if (s > mx) {
            float corr = __expf(mx - s);
            l *= corr;
#pragma unroll
            for (int i = 0; i < 16; i++) {
                acc[i].x *= corr; acc[i].y *= corr;
                acc[i].z *= corr; acc[i].w *= corr;
            }
            mx = s;
        }
        float p = __expf(s - mx);
        l += p;
#pragma unroll
        for (int i = 0; i < 16; i++) {
            float4 vv = V4[k * 16 + i];
            acc[i].x += p * vv.x; acc[i].y += p * vv.y;
            acc[i].z += p * vv.z; acc[i].w += p * vv.w;
        }
    }

    float inv = 1.f / l;
    float4* og = (float4*)(Op + base + (size_t)r * Dc + h * HDc);
#pragma unroll
    for (int i = 0; i < 16; i++) {
        float4 o;
        o.x = acc[i].x * inv; o.y = acc[i].y * inv;
        o.z = acc[i].z * inv; o.w = acc[i].w * inv;
        og[i] = o;
    }
}

// ---------------------------------------------------------------------------
// Global attention over the 32 gathered tokens. grid (B, H), 32 threads.
// Uses projected Q/K/V rows directly (gather commutes with linear layer).
// Writes packed GO[b*32+i, D].
// ---------------------------------------------------------------------------
__global__ __launch_bounds__(32) void global_attn_kernel(
    const float* __restrict__ Qp, const float* __restrict__ Kp,
    const float* __restrict__ Vp, const int* __restrict__ gidx,
    float* __restrict__ GO)
{
    __shared__ __align__(16) float Ks[32 * 64];
    __shared__ __align__(16) float Vs[32 * 64];
    __shared__ int sidx[32];

    const int b = blockIdx.x, h = blockIdx.y, tid = threadIdx.x;
    sidx[tid] = gidx[tid];
    __syncthreads();

    for (int idx = tid; idx < 32 * 64; idx += 32) {
        int rr = idx >> 6, c = idx & 63;
        size_t g = ((size_t)b * Sc + sidx[rr]) * Dc + h * HDc + c;
        Ks[idx] = Kp[g];
        Vs[idx] = Vp[g];
    }
    __syncthreads();

    const int i = tid;
    size_t qoff = ((size_t)b * Sc + sidx[i]) * Dc + h * HDc;
    float q[64];
#pragma unroll
    for (int d = 0; d < 64; d++) q[d] = Qp[qoff + d];

    float s[32];
    float mx = -1e30f;
    for (int j = 0; j < 32; j++) {
        float acc = 0.f;
#pragma unroll
        for (int d = 0; d < 64; d++) acc += q[d] * Ks[j * 64 + d];
        acc *= 0.125f;
        s[j] = acc;
        mx = fmaxf(mx, acc);
    }
    float l = 0.f;
    for (int j = 0; j < 32; j++) { s[j] = __expf(s[j] - mx); l += s[j]; }

    float acc[64];
#pragma unroll
    for (int d = 0; d < 64; d++) acc[d] = 0.f;
    for (int j = 0; j < 32; j++) {
        float p = s[j];
#pragma unroll
        for (int d = 0; d < 64; d++) acc[d] += p * Vs[j * 64 + d];
    }
    float inv = 1.f / l;
    float* o = GO + ((size_t)(b * 32 + i)) * Dc + h * HDc;
#pragma unroll
    for (int d = 0; d < 64; d++) o[d] = acc[d] * inv;
}

// ---------------------------------------------------------------------------
// Project the 128 global rows with Wo and scatter into Y at global_indices.
// grid (128, 4), 256 threads: block = (row, 256-col chunk).
// ---------------------------------------------------------------------------
__global__ __launch_bounds__(256) void global_proj_kernel(
    const float* __restrict__ GO, const float* __restrict__ Wo,
    const float* __restrict__ bo, const int* __restrict__ gidx,
    float* __restrict__ Y)
{
    __shared__ __align__(16) float xr[Dc];
    const int row = blockIdx.x;     // 0..127 = b*32 + i
    const int nb = blockIdx.y;
    const int tid = threadIdx.x;

    for (int i = tid; i < Dc; i += 256) xr[i] = GO[(size_t)row * Dc + i];
    __syncthreads();

    const int n = nb * 256 + tid;
    const float4* wr = (const float4*)(Wo + (size_t)n * Dc);
    const float4* x4 = (const float4*)xr;
    float s0 = 0.f, s1 = 0.f, s2 = 0.f, s3 = 0.f;
#pragma unroll 8
    for (int k = 0; k < Dc / 4; k++) {
        float4 w = wr[k];
        float4 x = x4[k];
        s0 += w.x * x.x; s1 += w.y * x.y; s2 += w.z * x.z; s3 += w.w * x.w;
    }
    float sum = s0 + s1 + s2 + s3 + bo[n];

    const int b = row >> 5, i = row & 31;
    const int tok = gidx[i];
    Y[((size_t)b * Sc + tok) * Dc + n] = sum;
}

// ---------------------------------------------------------------------------
extern "C" void kernel_launch(void* const* d_in, const int* in_sizes, int n_in,
                              void* d_out, int out_size)
{
    const float* query = (const float*)d_in[0];
    const float* key   = (const float*)d_in[1];
    const float* value = (const float*)d_in[2];
    const float* Wq = (const float*)d_in[3];
    const float* bq = (const float*)d_in[4];
    const float* Wk = (const float*)d_in[5];
    const float* bk = (const float*)d_in[6];
    const float* Wv = (const float*)d_in[7];
    const float* bv = (const float*)d_in[8];
    const float* Wo = (const float*)d_in[9];
    const float* bo = (const float*)d_in[10];
    const int* gidx = (const int*)d_in[11];
    float* out = (float*)d_out;

    float *Qb, *Kb, *Vb, *Ob, *GOb;
    cudaGetSymbolAddress((void**)&Qb, g_Q);
    cudaGetSymbolAddress((void**)&Kb, g_K);
    cudaGetSymbolAddress((void**)&Vb, g_V);
    cudaGetSymbolAddress((void**)&Ob, g_O);
    cudaGetSymbolAddress((void**)&GOb, g_GO);

    const int smem_attn = 2 * Wc * HDc * (int)sizeof(float);  // 64 KB
    cudaFuncSetAttribute(window_attn_kernel,
                         cudaFuncAttributeMaxDynamicSharedMemorySize, smem_attn);

    dim3 ggrid(Dc / 128, Mrows / 128);

    // Q/K/V projections
    gemm_bias_kernel<<<ggrid, 256>>>(query, Wq, bq, Qb, Mrows, Dc, Dc);
    gemm_bias_kernel<<<ggrid, 256>>>(key,   Wk, bk, Kb, Mrows, Dc, Dc);
    gemm_bias_kernel<<<ggrid, 256>>>(value, Wv, bv, Vb, Mrows, Dc, Dc);

    // Windowed attention
    window_attn_kernel<<<dim3(NWIN, Hc), 128, smem_attn>>>(Qb, Kb, Vb, Ob);

    // Output projection (full local result)
    gemm_bias_kernel<<<ggrid, 256>>>(Ob, Wo, bo, out, Mrows, Dc, Dc);

    // Global attention on the 32 gathered tokens, then project + scatter
    global_attn_kernel<<<dim3(Bc, Hc), 32>>>(Qb, Kb, Vb, gidx, GOb);
    global_proj_kernel<<<dim3(Bc * 32, Dc / 256), 256>>>(GOb, Wo, bo, gidx, out);
}

// round 3
// speedup vs baseline: 2.0266x; 2.0266x over previous
#include <cuda_runtime.h>
#include <cuda_bf16.h>
#include <cstdint>
#include <math.h>

// ---------------------------------------------------------------------------
// Problem constants
// ---------------------------------------------------------------------------
constexpr int Bc = 4;
constexpr int Sc = 4096;
constexpr int Dc = 1024;
constexpr int Hc = 16;
constexpr int HDc = 64;
constexpr int Wc = 128;
constexpr int NWIN = Bc * (Sc / Wc);   // 128 windows
constexpr int Mrows = Bc * Sc;         // 16384

// ---------------------------------------------------------------------------
// Scratch (device globals: allocation-free rule)
// ---------------------------------------------------------------------------
__device__ float g_Q[Mrows * Dc];
__device__ float g_K[Mrows * Dc];
__device__ float g_V[Mrows * Dc];
__device__ float g_O[Mrows * Dc];
__device__ float g_GO[Bc * 32 * Dc];

__device__ __align__(128) __nv_bfloat16 g_Xhi[Mrows * Dc];
__device__ __align__(128) __nv_bfloat16 g_Xlo[Mrows * Dc];
__device__ __align__(128) __nv_bfloat16 g_Whi[4][Dc * Dc];
__device__ __align__(128) __nv_bfloat16 g_Wlo[4][Dc * Dc];

// ---------------------------------------------------------------------------
// PTX helpers (baseline ISA only: cp.async / ldmatrix / mma.sync)
// ---------------------------------------------------------------------------
__device__ __forceinline__ uint32_t smem_to_u32(const void* p) {
    uint32_t a;
    asm("{ .reg .u64 t; cvta.to.shared.u64 t, %1; cvt.u32.u64 %0, t; }"
        : "=r"(a) : "l"(p));
    return a;
}

__device__ __forceinline__ void cp_async16(uint32_t dst, const void* src) {
    asm volatile("cp.async.cg.shared.global [%0], [%1], 16;"
                 :: "r"(dst), "l"(src));
}
#define CP_COMMIT() asm volatile("cp.async.commit_group;" ::: "memory")
#define CP_WAIT(n)  asm volatile("cp.async.wait_group %0;" :: "n"(n) : "memory")

#define LDSM_X4(r0, r1, r2, r3, addr) \
    asm volatile("ldmatrix.sync.aligned.m8n8.x4.shared.b16 {%0,%1,%2,%3}, [%4];" \
        : "=r"(r0), "=r"(r1), "=r"(r2), "=r"(r3) : "r"(addr))

#define MMA16816(d, a, b0v, b1v) \
    asm volatile("mma.sync.aligned.m16n8k16.row.col.f32.bf16.bf16.f32 " \
        "{%0,%1,%2,%3}, {%4,%5,%6,%7}, {%8,%9}, {%0,%1,%2,%3};" \
        : "+f"((d)[0]), "+f"((d)[1]), "+f"((d)[2]), "+f"((d)[3]) \
        : "r"((a)[0]), "r"((a)[1]), "r"((a)[2]), "r"((a)[3]), \
          "r"(b0v), "r"(b1v))

// ---------------------------------------------------------------------------
// fp32 -> (bf16 hi, bf16 lo) split
// ---------------------------------------------------------------------------
__global__ __launch_bounds__(256) void cvt_pair_kernel(
    const float* __restrict__ x, __nv_bfloat16* __restrict__ hi,
    __nv_bfloat16* __restrict__ lo, int n4)
{
    int i = blockIdx.x * 256 + threadIdx.x;
    if (i >= n4) return;
    float4 v = ((const float4*)x)[i];
    __nv_bfloat16 h0 = __float2bfloat16_rn(v.x);
    __nv_bfloat16 h1 = __float2bfloat16_rn(v.y);
    __nv_bfloat16 h2 = __float2bfloat16_rn(v.z);
    __nv_bfloat16 h3 = __float2bfloat16_rn(v.w);
    __nv_bfloat16 l0 = __float2bfloat16_rn(v.x - __bfloat162float(h0));
    __nv_bfloat16 l1 = __float2bfloat16_rn(v.y - __bfloat162float(h1));
    __nv_bfloat16 l2 = __float2bfloat16_rn(v.z - __bfloat162float(h2));
    __nv_bfloat16 l3 = __float2bfloat16_rn(v.w - __bfloat162float(h3));
    __nv_bfloat162* hp = (__nv_bfloat162*)hi;
    __nv_bfloat162* lp = (__nv_bfloat162*)lo;
    __nv_bfloat162 a, b;
    a.x = h0; a.y = h1; b.x = h2; b.y = h3;
    hp[2 * i] = a; hp[2 * i + 1] = b;
    a.x = l0; a.y = l1; b.x = l2; b.y = l3;
    lp[2 * i] = a; lp[2 * i + 1] = b;
}

// ---------------------------------------------------------------------------
// mma.sync GEMM: Y[m,n] = sum_k X[m,k]*Wt[n,k] + bias[n]  (bf16 hi/lo 3-pass)
// BM=128 BN=128 BK=32, 256 threads (8 warps 2x4), double-buffered cp.async.
// Smem rows: 64B data + 16B pad = 80B stride (conflict-free ldmatrix).
// ---------------------------------------------------------------------------
constexpr int BM = 128, BN = 128, BK = 32;
constexpr int ROWB = 80;                       // bytes per smem row
constexpr int TILE_B = 128 * ROWB;             // 10240 per matrix tile
constexpr int STAGE_B = 4 * TILE_B;            // Ahi,Alo,Bhi,Blo = 40960
constexpr int SMEM_GEMM = 2 * STAGE_B;         // 81920
constexpr int NCHUNK = Dc / BK;                // 32

__global__ __launch_bounds__(256, 2) void gemm_mma_kernel(
    const __nv_bfloat16* __restrict__ Ahi, const __nv_bfloat16* __restrict__ Alo,
    const __nv_bfloat16* __restrict__ Bhi, const __nv_bfloat16* __restrict__ Blo,
    const float* __restrict__ bias, float* __restrict__ Y)
{
    extern __shared__ __align__(128) char smem[];
    const uint32_t sbase = smem_to_u32(smem);
    const int tid = threadIdx.x;
    const int lane = tid & 31;
    const int wid = tid >> 5;
    const int wm = wid >> 2;        // 0..1  -> 64-row slab
    const int wn = wid & 3;         // 0..3  -> 32-col slab
    const int m0 = blockIdx.y * BM;
    const int n0 = blockIdx.x * BN;

    float acc[4][4][4];
#pragma unroll
    for (int mi = 0; mi < 4; mi++)
#pragma unroll
        for (int nt = 0; nt < 4; nt++)
#pragma unroll
            for (int e = 0; e < 4; e++) acc[mi][nt][e] = 0.f;

    auto issue = [&](int c, int s) {
        const int k0 = c * BK;
        const uint32_t sb = sbase + s * STAGE_B;
#pragma unroll
        for (int i = 0; i < 4; i++) {               // A: hi then lo
            int idx = tid + i * 256;                // 0..1023
            const __nv_bfloat16* src = (idx & 512) ? Alo : Ahi;
            int r = (idx >> 2) & 127, col = idx & 3;
            uint32_t dst = sb + ((idx & 512) ? TILE_B : 0) + r * ROWB + col * 16;
            cp_async16(dst, src + (size_t)(m0 + r) * Dc + k0 + col * 8);
        }
#pragma unroll
        for (int i = 0; i < 4; i++) {               // B: hi then lo
            int idx = tid + i * 256;
            const __nv_bfloat16* src = (idx & 512) ? Blo : Bhi;
            int r = (idx >> 2) & 127, col = idx & 3;
            uint32_t dst = sb + 2 * TILE_B + ((idx & 512) ? TILE_B : 0) + r * ROWB + col * 16;
            cp_async16(dst, src + (size_t)(n0 + r) * Dc + k0 + col * 8);
        }
        CP_COMMIT();
    };

    issue(0, 0);
    issue(1, 1);

    for (int c = 0; c < NCHUNK; c++) {
        const int s = c & 1;
        if (c < NCHUNK - 2) { CP_WAIT(1); } else { CP_WAIT(0); }
        __syncthreads();

        const uint32_t sb = sbase + s * STAGE_B;
        const uint32_t a_hi = sb;
        const uint32_t a_lo = sb + TILE_B;
        const uint32_t b_hi = sb + 2 * TILE_B;
        const uint32_t b_lo = sb + 3 * TILE_B;

#pragma unroll
        for (int ks = 0; ks < 2; ks++) {
            const uint32_t kb = ks * 32 + ((lane >> 4) << 4);      // A k-byte sel
            const uint32_t kbB = ks * 32 + (((lane >> 3) & 1) << 4); // B k-byte sel
            uint32_t a[4][4], bh[4][2], bl[4][2];

#pragma unroll
            for (int mi = 0; mi < 4; mi++) {
                uint32_t addr = a_hi + (wm * 64 + mi * 16 + (lane & 15)) * ROWB + kb;
                LDSM_X4(a[mi][0], a[mi][1], a[mi][2], a[mi][3], addr);
            }
#pragma unroll
            for (int p = 0; p < 2; p++) {
                uint32_t roff = (wn * 32 + p * 16 + (lane & 7) + ((lane >> 4) << 3)) * ROWB + kbB;
                uint32_t r0, r1, r2, r3;
                LDSM_X4(r0, r1, r2, r3, b_hi + roff);
                bh[2 * p][0] = r0; bh[2 * p][1] = r1;
                bh[2 * p + 1][0] = r2; bh[2 * p + 1][1] = r3;
                LDSM_X4(r0, r1, r2, r3, b_lo + roff);
                bl[2 * p][0] = r0; bl[2 * p][1] = r1;
                bl[2 * p + 1][0] = r2; bl[2 * p + 1][1] = r3;
            }
            // pass 1: Ahi * Bhi ; pass 2: Ahi * Blo
#pragma unroll
            for (int mi = 0; mi < 4; mi++)
#pragma unroll
                for (int nt = 0; nt < 4; nt++) {
                    MMA16816(acc[mi][nt], a[mi], bh[nt][0], bh[nt][1]);
                    MMA16816(acc[mi][nt], a[mi], bl[nt][0], bl[nt][1]);
                }
            // pass 3: Alo * Bhi
#pragma unroll
            for (int mi = 0; mi < 4; mi++) {
                uint32_t addr = a_lo + (wm * 64 + mi * 16 + (lane & 15)) * ROWB + kb;
                LDSM_X4(a[mi][0], a[mi][1], a[mi][2], a[mi][3], addr);
            }
#pragma unroll
            for (int mi = 0; mi < 4; mi++)
#pragma unroll
                for (int nt = 0; nt < 4; nt++)
                    MMA16816(acc[mi][nt], a[mi], bh[nt][0], bh[nt][1]);
        }
        __syncthreads();
        if (c + 2 < NCHUNK) issue(c + 2, s);
    }

    // Epilogue: registers -> gmem with fused bias (float2, coalesced)
#pragma unroll
    for (int nt = 0; nt < 4; nt++) {
        const int n = n0 + wn * 32 + nt * 8 + 2 * (lane & 3);
        const float b0 = bias[n], b1 = bias[n + 1];
#pragma unroll
        for (int mi = 0; mi < 4; mi++) {
            const int r0 = m0 + wm * 64 + mi * 16 + (lane >> 2);
            float2 v0, v1;
            v0.x = acc[mi][nt][0] + b0; v0.y = acc[mi][nt][1] + b1;
            v1.x = acc[mi][nt][2] + b0; v1.y = acc[mi][nt][3] + b1;
            *(float2*)&Y[(size_t)r0 * Dc + n] = v0;
            *(float2*)&Y[(size_t)(r0 + 8) * Dc + n] = v1;
        }
    }
}

// ---------------------------------------------------------------------------
// Windowed attention: grid (NWIN, H), 128 threads; thread = one query row.
// ---------------------------------------------------------------------------
__global__ __launch_bounds__(128) void window_attn_kernel(
    const float* __restrict__ Qp, const float* __restrict__ Kp,
    const float* __restrict__ Vp, float* __restrict__ Op)
{
    extern __shared__ __align__(16) float sm[];
    float* Ks = sm;
    float* Vs = sm + Wc * HDc;

    const int win = blockIdx.x;
    const int h = blockIdx.y;
    const size_t base = (size_t)win * Wc * Dc;
    const int tid = threadIdx.x;

    for (int idx = tid; idx < Wc * HDc; idx += 128) {
        int r = idx >> 6, c = idx & 63;
        size_t g = base + (size_t)r * Dc + h * HDc + c;
        Ks[idx] = Kp[g];
        Vs[idx] = Vp[g];
    }
    __syncthreads();

    const int r = tid;
    float4 q[16];
    const float4* qg = (const float4*)(Qp + base + (size_t)r * Dc + h * HDc);
#pragma unroll
    for (int i = 0; i < 16; i++) q[i] = qg[i];

    float mx = -1e30f, l = 0.f;
    float4 acc[16];
#pragma unroll
    for (int i = 0; i < 16; i++) acc[i] = make_float4(0.f, 0.f, 0.f, 0.f);

    const float4* K4 = (const float4*)Ks;
    const float4* V4 = (const float4*)Vs;

    for (int k = 0; k < Wc; k++) {
        float s0 = 0.f, s1 = 0.f, s2 = 0.f, s3 = 0.f;
#pragma unroll
        for (int i = 0; i < 16; i++) {
            float4 kv = K4[k * 16 + i];
            s0 += q[i].x * kv.x; s1 += q[i].y * kv.y;
            s2 += q[i].z * kv.z; s3 += q[i].w * kv.w;
        }
        float s = (s0 + s1 + s2 + s3) * 0.125f;
        if (s > mx) {
            float corr = __expf(mx - s);
            l *= corr;
#pragma unroll
            for (int i = 0; i < 16; i++) {
                acc[i].x *= corr; acc[i].y *= corr;
                acc[i].z *= corr; acc[i].w *= corr;
            }
            mx = s;
        }
        float p = __expf(s - mx);
        l += p;
#pragma unroll
        for (int i = 0; i < 16; i++) {
            float4 vv = V4[k * 16 + i];
            acc[i].x += p * vv.x; acc[i].y += p * vv.y;
            acc[i].z += p * vv.z; acc[i].w += p * vv.w;
        }
    }

    float inv = 1.f / l;
    float4* og = (float4*)(Op + base + (size_t)r * Dc + h * HDc);
#pragma unroll
    for (int i = 0; i < 16; i++) {
        float4 o;
        o.x = acc[i].x * inv; o.y = acc[i].y * inv;
        o.z = acc[i].z * inv; o.w = acc[i].w * inv;
        og[i] = o;
    }
}

// ---------------------------------------------------------------------------
// Global attention over 32 gathered tokens. grid (B, H), 32 threads.
// ---------------------------------------------------------------------------
__global__ __launch_bounds__(32) void global_attn_kernel(
    const float* __restrict__ Qp, const float* __restrict__ Kp,
    const float* __restrict__ Vp, const int* __restrict__ gidx,
    float* __restrict__ GO)
{
    __shared__ __align__(16) float Ks[32 * 64];
    __shared__ __align__(16) float Vs[32 * 64];
    __shared__ int sidx[32];

    const int b = blockIdx.x, h = blockIdx.y, tid = threadIdx.x;
    sidx[tid] = gidx[tid];
    __syncthreads();

    for (int idx = tid; idx < 32 * 64; idx += 32) {
        int rr = idx >> 6, c = idx & 63;
        size_t g = ((size_t)b * Sc + sidx[rr]) * Dc + h * HDc + c;
        Ks[idx] = Kp[g];
        Vs[idx] = Vp[g];
    }
    __syncthreads();

    const int i = tid;
    size_t qoff = ((size_t)b * Sc + sidx[i]) * Dc + h * HDc;
    float q[64];
#pragma unroll
    for (int d = 0; d < 64; d++) q[d] = Qp[qoff + d];

    float s[32];
    float mx = -1e30f;
    for (int j = 0; j < 32; j++) {
        float a = 0.f;
#pragma unroll
        for (int d = 0; d < 64; d++) a += q[d] * Ks[j * 64 + d];
        a *= 0.125f;
        s[j] = a;
        mx = fmaxf(mx, a);
    }
    float l = 0.f;
    for (int j = 0; j < 32; j++) { s[j] = __expf(s[j] - mx); l += s[j]; }

    float acc[64];
#pragma unroll
    for (int d = 0; d < 64; d++) acc[d] = 0.f;
    for (int j = 0; j < 32; j++) {
        float p = s[j];
#pragma unroll
        for (int d = 0; d < 64; d++) acc[d] += p * Vs[j * 64 + d];
    }
    float inv = 1.f / l;
    float* o = GO + ((size_t)(b * 32 + i)) * Dc + h * HDc;
#pragma unroll
    for (int d = 0; d < 64; d++) o[d] = acc[d] * inv;
}

// ---------------------------------------------------------------------------
// Project 128 global rows with Wo (fp32), scatter into Y at global_indices.
// ---------------------------------------------------------------------------
__global__ __launch_bounds__(256) void global_proj_kernel(
    const float* __restrict__ GO, const float* __restrict__ Wo,
    const float* __restrict__ bo, const int* __restrict__ gidx,
    float* __restrict__ Y)
{
    __shared__ __align__(16) float xr[Dc];
    const int row = blockIdx.x;
    const int nb = blockIdx.y;
    const int tid = threadIdx.x;

    for (int i = tid; i < Dc; i += 256) xr[i] = GO[(size_t)row * Dc + i];
    __syncthreads();

    const int n = nb * 256 + tid;
    const float4* wr = (const float4*)(Wo + (size_t)n * Dc);
    const float4* x4 = (const float4*)xr;
    float s0 = 0.f, s1 = 0.f, s2 = 0.f, s3 = 0.f;
#pragma unroll 8
    for (int k = 0; k < Dc / 4; k++) {
        float4 w = wr[k];
        float4 x = x4[k];
        s0 += w.x * x.x; s1 += w.y * x.y; s2 += w.z * x.z; s3 += w.w * x.w;
    }
    float sum = s0 + s1 + s2 + s3 + bo[n];

    const int b = row >> 5, i = row & 31;
    const int tok = gidx[i];
    Y[((size_t)b * Sc + tok) * Dc + n] = sum;
}

// ---------------------------------------------------------------------------
extern "C" void kernel_launch(void* const* d_in, const int* in_sizes, int n_in,
                              void* d_out, int out_size)
{
    const float* query = (const float*)d_in[0];
    const float* key   = (const float*)d_in[1];
    const float* value = (const float*)d_in[2];
    const float* Wq = (const float*)d_in[3];
    const float* bq = (const float*)d_in[4];
    const float* Wk = (const float*)d_in[5];
    const float* bk = (const float*)d_in[6];
    const float* Wv = (const float*)d_in[7];
    const float* bv = (const float*)d_in[8];
    const float* Wo = (const float*)d_in[9];
    const float* bo = (const float*)d_in[10];
    const int* gidx = (const int*)d_in[11];
    float* out = (float*)d_out;

    float *Qb, *Kb, *Vb, *Ob, *GOb;
    cudaGetSymbolAddress((void**)&Qb, g_Q);
    cudaGetSymbolAddress((void**)&Kb, g_K);
    cudaGetSymbolAddress((void**)&Vb, g_V);
    cudaGetSymbolAddress((void**)&Ob, g_O);
    cudaGetSymbolAddress((void**)&GOb, g_GO);
    __nv_bfloat16 *Xhi, *Xlo, *Whi, *Wlo;
    cudaGetSymbolAddress((void**)&Xhi, g_Xhi);
    cudaGetSymbolAddress((void**)&Xlo, g_Xlo);
    cudaGetSymbolAddress((void**)&Whi, g_Whi);
    cudaGetSymbolAddress((void**)&Wlo, g_Wlo);

    cudaFuncSetAttribute(gemm_mma_kernel,
                         cudaFuncAttributeMaxDynamicSharedMemorySize, SMEM_GEMM);
    const int smem_attn = 2 * Wc * HDc * (int)sizeof(float);  // 64 KB
    cudaFuncSetAttribute(window_attn_kernel,
                         cudaFuncAttributeMaxDynamicSharedMemorySize, smem_attn);

    const int WN4 = Dc * Dc / 4;
    const int XN4 = Mrows * Dc / 4;
    const dim3 ggrid(Dc / BN, Mrows / BM);   // (8, 128)

    // Convert the four weight matrices to hi/lo
    const float* Ws[4] = {Wq, Wk, Wv, Wo};
    for (int w = 0; w < 4; w++)
        cvt_pair_kernel<<<(WN4 + 255) / 256, 256>>>(
            Ws[w], Whi + (size_t)w * Dc * Dc, Wlo + (size_t)w * Dc * Dc, WN4);

    // Q projection
    cvt_pair_kernel<<<(XN4 + 255) / 256, 256>>>(query, Xhi, Xlo, XN4);
    gemm_mma_kernel<<<ggrid, 256, SMEM_GEMM>>>(Xhi, Xlo, Whi, Wlo, bq, Qb);
    // K projection
    cvt_pair_kernel<<<(XN4 + 255) / 256, 256>>>(key, Xhi, Xlo, XN4);
    gemm_mma_kernel<<<ggrid, 256, SMEM_GEMM>>>(
        Xhi, Xlo, Whi + (size_t)1 * Dc * Dc, Wlo + (size_t)1 * Dc * Dc, bk, Kb);
    // V projection
    cvt_pair_kernel<<<(XN4 + 255) / 256, 256>>>(value, Xhi, Xlo, XN4);
    gemm_mma_kernel<<<ggrid, 256, SMEM_GEMM>>>(
        Xhi, Xlo, Whi + (size_t)2 * Dc * Dc, Wlo + (size_t)2 * Dc * Dc, bv, Vb);

    // Windowed attention
    window_attn_kernel<<<dim3(NWIN, Hc), 128, smem_attn>>>(Qb, Kb, Vb, Ob);

    // Output projection
    cvt_pair_kernel<<<(XN4 + 255) / 256, 256>>>(Ob, Xhi, Xlo, XN4);
    gemm_mma_kernel<<<ggrid, 256, SMEM_GEMM>>>(
        Xhi, Xlo, Whi + (size_t)3 * Dc * Dc, Wlo + (size_t)3 * Dc * Dc, bo, out);

    // Global attention on gathered tokens, project + scatter (overwrites rows)
    global_attn_kernel<<<dim3(Bc, Hc), 32>>>(Qb, Kb, Vb, gidx, GOb);
    global_proj_kernel<<<dim3(Bc * 32, Dc / 256), 256>>>(GOb, Wo, bo, gidx, out);
}

// round 4
// speedup vs baseline: 2.4019x; 1.1852x over previous
#include <cuda_runtime.h>
#include <cuda_bf16.h>
#include <cstdint>
#include <math.h>

// ---------------------------------------------------------------------------
// Problem constants
// ---------------------------------------------------------------------------
constexpr int Bc = 4;
constexpr int Sc = 4096;
constexpr int Dc = 1024;
constexpr int Hc = 16;
constexpr int HDc = 64;
constexpr int Wc = 128;
constexpr int NWIN = Bc * (Sc / Wc);   // 128 windows
constexpr int Mrows = Bc * Sc;         // 16384

// ---------------------------------------------------------------------------
// Scratch (device globals: allocation-free rule)
// ---------------------------------------------------------------------------
__device__ float g_Q[Mrows * Dc];
__device__ float g_K[Mrows * Dc];
__device__ float g_V[Mrows * Dc];
__device__ __align__(128) float g_Xr[Mrows * Dc];      // tf32-rounded activations
__device__ __align__(128) float g_Wr[4][Dc * Dc];      // tf32-rounded weights
__device__ float g_GO[Bc * 32 * Dc];

// ---------------------------------------------------------------------------
// PTX helpers (baseline ISA only: cp.async / mma.sync tf32)
// ---------------------------------------------------------------------------
__device__ __forceinline__ uint32_t smem_to_u32(const void* p) {
    uint32_t a;
    asm("{ .reg .u64 t; cvta.to.shared.u64 t, %1; cvt.u32.u64 %0, t; }"
        : "=r"(a) : "l"(p));
    return a;
}

__device__ __forceinline__ void cp_async16(uint32_t dst, const void* src) {
    asm volatile("cp.async.cg.shared.global [%0], [%1], 16;"
                 :: "r"(dst), "l"(src));
}
#define CP_COMMIT() asm volatile("cp.async.commit_group;" ::: "memory")
#define CP_WAIT(n)  asm volatile("cp.async.wait_group %0;" :: "n"(n) : "memory")

__device__ __forceinline__ uint32_t f32_to_tf32(float x) {
    uint32_t r;
    asm("cvt.rna.tf32.f32 %0, %1;" : "=r"(r) : "f"(x));
    return r;
}

#define MMA_TF32(d, a0v, a1v, a2v, a3v, b0v, b1v) \
    asm volatile("mma.sync.aligned.m16n8k8.row.col.f32.tf32.tf32.f32 " \
        "{%0,%1,%2,%3}, {%4,%5,%6,%7}, {%8,%9}, {%0,%1,%2,%3};" \
        : "+f"((d)[0]), "+f"((d)[1]), "+f"((d)[2]), "+f"((d)[3]) \
        : "r"(a0v), "r"(a1v), "r"(a2v), "r"(a3v), "r"(b0v), "r"(b1v))

// ---------------------------------------------------------------------------
// fp32 -> tf32-rounded fp32 (elementwise, vectorized)
// ---------------------------------------------------------------------------
__global__ __launch_bounds__(256) void round_tf32_kernel(
    const float* __restrict__ x, float* __restrict__ y, int n4)
{
    int i = blockIdx.x * 256 + threadIdx.x;
    if (i >= n4) return;
    float4 v = ((const float4*)x)[i];
    uint4 o;
    o.x = f32_to_tf32(v.x);
    o.y = f32_to_tf32(v.y);
    o.z = f32_to_tf32(v.z);
    o.w = f32_to_tf32(v.w);
    ((uint4*)y)[i] = o;
}

// ---------------------------------------------------------------------------
// tf32 mma.sync GEMM: Y[m,n] = sum_k X[m,k]*Wt[n,k] + bias[n]
// Inputs pre-rounded to tf32. BM=BN=128, BK=32, 256 thr (8 warps 2x4),
// double-buffered cp.async. Smem rows: 32 floats + 4 pad = 36 (bank-clean:
// fragment lanes hit banks 4*g + t, all distinct).
// ---------------------------------------------------------------------------
constexpr int BM = 128, BN = 128, BK = 32;
constexpr int ROWF = 36;                        // floats per smem row
constexpr int TILE_B = 128 * ROWF * 4;          // 18432 B per matrix tile
constexpr int STAGE_B = 2 * TILE_B;             // 36864
constexpr int SMEM_GEMM = 2 * STAGE_B;          // 73728
constexpr int NCHUNK = Dc / BK;                 // 32

__global__ __launch_bounds__(256, 2) void gemm_tf32_kernel(
    const float* __restrict__ A, const float* __restrict__ Bm,
    const float* __restrict__ bias, float* __restrict__ Y)
{
    extern __shared__ __align__(128) char smem[];
    const uint32_t sbase = smem_to_u32(smem);
    const int tid = threadIdx.x;
    const int lane = tid & 31;
    const int wid = tid >> 5;
    const int wm = wid >> 2;        // 0..1 -> 64-row slab
    const int wn = wid & 3;         // 0..3 -> 32-col slab
    const int m0 = blockIdx.y * BM;
    const int n0 = blockIdx.x * BN;
    const int g = lane >> 2;        // groupID 0..7
    const int t = lane & 3;         // thread-in-group 0..3

    float acc[4][4][4];
#pragma unroll
    for (int mi = 0; mi < 4; mi++)
#pragma unroll
        for (int nt = 0; nt < 4; nt++)
#pragma unroll
            for (int e = 0; e < 4; e++) acc[mi][nt][e] = 0.f;

    auto issue = [&](int c, int s) {
        const int k0 = c * BK;
        const uint32_t sb = sbase + s * STAGE_B;
#pragma unroll
        for (int i = 0; i < 4; i++) {               // A: 128 rows x 8 chunks
            int idx = tid + i * 256;                // 0..1023
            int r = idx >> 3, ch = idx & 7;
            cp_async16(sb + r * (ROWF * 4) + ch * 16,
                       A + (size_t)(m0 + r) * Dc + k0 + ch * 4);
        }
#pragma unroll
        for (int i = 0; i < 4; i++) {               // B: 128 rows x 8 chunks
            int idx = tid + i * 256;
            int r = idx >> 3, ch = idx & 7;
            cp_async16(sb + TILE_B + r * (ROWF * 4) + ch * 16,
                       Bm + (size_t)(n0 + r) * Dc + k0 + ch * 4);
        }
        CP_COMMIT();
    };

    issue(0, 0);
    issue(1, 1);

    for (int c = 0; c < NCHUNK; c++) {
        const int s = c & 1;
        if (c < NCHUNK - 2) { CP_WAIT(1); } else { CP_WAIT(0); }
        __syncthreads();

        const float* As = (const float*)(smem + s * STAGE_B);
        const float* Bs = (const float*)(smem + s * STAGE_B + TILE_B);

#pragma unroll
        for (int ks = 0; ks < 4; ks++) {
            const int kk = ks * 8;
            uint32_t bf[4][2];
#pragma unroll
            for (int nt = 0; nt < 4; nt++) {
                const int n = wn * 32 + nt * 8 + g;
                bf[nt][0] = __float_as_uint(Bs[n * ROWF + kk + t]);
                bf[nt][1] = __float_as_uint(Bs[n * ROWF + kk + 4 + t]);
            }
#pragma unroll
            for (int mi = 0; mi < 4; mi++) {
                const int m = wm * 64 + mi * 16 + g;
                uint32_t a0 = __float_as_uint(As[m * ROWF + kk + t]);
                uint32_t a1 = __float_as_uint(As[(m + 8) * ROWF + kk + t]);
                uint32_t a2 = __float_as_uint(As[m * ROWF + kk + 4 + t]);
                uint32_t a3 = __float_as_uint(As[(m + 8) * ROWF + kk + 4 + t]);
#pragma unroll
                for (int nt = 0; nt < 4; nt++)
                    MMA_TF32(acc[mi][nt], a0, a1, a2, a3, bf[nt][0], bf[nt][1]);
            }
        }
        __syncthreads();
        if (c + 2 < NCHUNK) issue(c + 2, s);
    }

    // Epilogue: registers -> gmem with fused bias (float2, coalesced)
#pragma unroll
    for (int nt = 0; nt < 4; nt++) {
        const int n = n0 + wn * 32 + nt * 8 + 2 * (lane & 3);
        const float b0 = bias[n], b1 = bias[n + 1];
#pragma unroll
        for (int mi = 0; mi < 4; mi++) {
            const int r0 = m0 + wm * 64 + mi * 16 + (lane >> 2);
            float2 v0, v1;
            v0.x = acc[mi][nt][0] + b0; v0.y = acc[mi][nt][1] + b1;
            v1.x = acc[mi][nt][2] + b0; v1.y = acc[mi][nt][3] + b1;
            *(float2*)&Y[(size_t)r0 * Dc + n] = v0;
            *(float2*)&Y[(size_t)(r0 + 8) * Dc + n] = v1;
        }
    }
}

// ---------------------------------------------------------------------------
// Windowed attention, chunked softmax. grid (NWIN, H), 128 threads.
// Output written tf32-rounded (feeds the tf32 output projection directly).
// ---------------------------------------------------------------------------
__global__ __launch_bounds__(128) void window_attn_kernel(
    const float* __restrict__ Qp, const float* __restrict__ Kp,
    const float* __restrict__ Vp, float* __restrict__ Op)
{
    extern __shared__ __align__(16) float sm[];
    float* Ks = sm;
    float* Vs = sm + Wc * HDc;

    const int win = blockIdx.x;
    const int h = blockIdx.y;
    const size_t base = (size_t)win * Wc * Dc;
    const int tid = threadIdx.x;

    for (int idx = tid; idx < Wc * HDc; idx += 128) {
        int r = idx >> 6, c = idx & 63;
        size_t gg = base + (size_t)r * Dc + h * HDc + c;
        Ks[idx] = Kp[gg];
        Vs[idx] = Vp[gg];
    }
    __syncthreads();

    const int r = tid;
    float4 q[16];
    const float4* qg = (const float4*)(Qp + base + (size_t)r * Dc + h * HDc);
#pragma unroll
    for (int i = 0; i < 16; i++) q[i] = qg[i];

    float mx = -1e30f, l = 0.f;
    float4 acc[16];
#pragma unroll
    for (int i = 0; i < 16; i++) acc[i] = make_float4(0.f, 0.f, 0.f, 0.f);

    const float4* K4 = (const float4*)Ks;
    const float4* V4 = (const float4*)Vs;

    for (int kc = 0; kc < Wc; kc += 8) {
        float sc[8];
        float cmax = -1e30f;
#pragma unroll
        for (int j = 0; j < 8; j++) {
            float s0 = 0.f, s1 = 0.f, s2 = 0.f, s3 = 0.f;
#pragma unroll
            for (int i = 0; i < 16; i++) {
                float4 kv = K4[(kc + j) * 16 + i];
                s0 += q[i].x * kv.x; s1 += q[i].y * kv.y;
                s2 += q[i].z * kv.z; s3 += q[i].w * kv.w;
            }
            sc[j] = (s0 + s1 + s2 + s3) * 0.125f;
            cmax = fmaxf(cmax, sc[j]);
        }
        if (cmax > mx) {
            float corr = __expf(mx - cmax);
            l *= corr;
#pragma unroll
            for (int i = 0; i < 16; i++) {
                acc[i].x *= corr; acc[i].y *= corr;
                acc[i].z *= corr; acc[i].w *= corr;
            }
            mx = cmax;
        }
#pragma unroll
        for (int j = 0; j < 8; j++) {
            float p = __expf(sc[j] - mx);
            l += p;
#pragma unroll
            for (int i = 0; i < 16; i++) {
                float4 vv = V4[(kc + j) * 16 + i];
                acc[i].x += p * vv.x; acc[i].y += p * vv.y;
                acc[i].z += p * vv.z; acc[i].w += p * vv.w;
            }
        }
    }

    float inv = 1.f / l;
    uint4* og = (uint4*)(Op + base + (size_t)r * Dc + h * HDc);
#pragma unroll
    for (int i = 0; i < 16; i++) {
        uint4 o;
        o.x = f32_to_tf32(acc[i].x * inv);
        o.y = f32_to_tf32(acc[i].y * inv);
        o.z = f32_to_tf32(acc[i].z * inv);
        o.w = f32_to_tf32(acc[i].w * inv);
        og[i] = o;
    }
}

// ---------------------------------------------------------------------------
// Global attention over 32 gathered tokens. grid (B, H), 32 threads.
// ---------------------------------------------------------------------------
__global__ __launch_bounds__(32) void global_attn_kernel(
    const float* __restrict__ Qp, const float* __restrict__ Kp,
    const float* __restrict__ Vp, const int* __restrict__ gidx,
    float* __restrict__ GO)
{
    __shared__ __align__(16) float Ks[32 * 64];
    __shared__ __align__(16) float Vs[32 * 64];
    __shared__ int sidx[32];

    const int b = blockIdx.x, h = blockIdx.y, tid = threadIdx.x;
    sidx[tid] = gidx[tid];
    __syncthreads();

    for (int idx = tid; idx < 32 * 64; idx += 32) {
        int rr = idx >> 6, c = idx & 63;
        size_t gg = ((size_t)b * Sc + sidx[rr]) * Dc + h * HDc + c;
        Ks[idx] = Kp[gg];
        Vs[idx] = Vp[gg];
    }
    __syncthreads();

    const int i = tid;
    size_t qoff = ((size_t)b * Sc + sidx[i]) * Dc + h * HDc;
    float q[64];
#pragma unroll
    for (int d = 0; d < 64; d++) q[d] = Qp[qoff + d];

    float s[32];
    float mx = -1e30f;
    for (int j = 0; j < 32; j++) {
        float a = 0.f;
#pragma unroll
        for (int d = 0; d < 64; d++) a += q[d] * Ks[j * 64 + d];
        a *= 0.125f;
        s[j] = a;
        mx = fmaxf(mx, a);
    }
    float l = 0.f;
    for (int j = 0; j < 32; j++) { s[j] = __expf(s[j] - mx); l += s[j]; }

    float acc[64];
#pragma unroll
    for (int d = 0; d < 64; d++) acc[d] = 0.f;
    for (int j = 0; j < 32; j++) {
        float p = s[j];
#pragma unroll
        for (int d = 0; d < 64; d++) acc[d] += p * Vs[j * 64 + d];
    }
    float inv = 1.f / l;
    float* o = GO + ((size_t)(b * 32 + i)) * Dc + h * HDc;
#pragma unroll
    for (int d = 0; d < 64; d++) o[d] = acc[d] * inv;
}

// ---------------------------------------------------------------------------
// Project 128 global rows with Wo (fp32 exact), scatter into Y.
// ---------------------------------------------------------------------------
__global__ __launch_bounds__(256) void global_proj_kernel(
    const float* __restrict__ GO, const float* __restrict__ Wo,
    const float* __restrict__ bo, const int* __restrict__ gidx,
    float* __restrict__ Y)
{
    __shared__ __align__(16) float xr[Dc];
    const int row = blockIdx.x;
    const int nb = blockIdx.y;
    const int tid = threadIdx.x;

    for (int i = tid; i < Dc; i += 256) xr[i] = GO[(size_t)row * Dc + i];
    __syncthreads();

    const int n = nb * 256 + tid;
    const float4* wr = (const float4*)(Wo + (size_t)n * Dc);
    const float4* x4 = (const float4*)xr;
    float s0 = 0.f, s1 = 0.f, s2 = 0.f, s3 = 0.f;
#pragma unroll 8
    for (int k = 0; k < Dc / 4; k++) {
        float4 w = wr[k];
        float4 x = x4[k];
        s0 += w.x * x.x; s1 += w.y * x.y; s2 += w.z * x.z; s3 += w.w * x.w;
    }
    float sum = s0 + s1 + s2 + s3 + bo[n];

    const int b = row >> 5, i = row & 31;
    const int tok = gidx[i];
    Y[((size_t)b * Sc + tok) * Dc + n] = sum;
}

// ---------------------------------------------------------------------------
extern "C" void kernel_launch(void* const* d_in, const int* in_sizes, int n_in,
                              void* d_out, int out_size)
{
    const float* query = (const float*)d_in[0];
    const float* key   = (const float*)d_in[1];
    const float* value = (const float*)d_in[2];
    const float* Wq = (const float*)d_in[3];
    const float* bq = (const float*)d_in[4];
    const float* Wk = (const float*)d_in[5];
    const float* bk = (const float*)d_in[6];
    const float* Wv = (const float*)d_in[7];
    const float* bv = (const float*)d_in[8];
    const float* Wo = (const float*)d_in[9];
    const float* bo = (const float*)d_in[10];
    const int* gidx = (const int*)d_in[11];
    float* out = (float*)d_out;

    float *Qb, *Kb, *Vb, *Xr, *Wr, *GOb;
    cudaGetSymbolAddress((void**)&Qb, g_Q);
    cudaGetSymbolAddress((void**)&Kb, g_K);
    cudaGetSymbolAddress((void**)&Vb, g_V);
    cudaGetSymbolAddress((void**)&Xr, g_Xr);
    cudaGetSymbolAddress((void**)&Wr, g_Wr);
    cudaGetSymbolAddress((void**)&GOb, g_GO);

    cudaFuncSetAttribute(gemm_tf32_kernel,
                         cudaFuncAttributeMaxDynamicSharedMemorySize, SMEM_GEMM);
    const int smem_attn = 2 * Wc * HDc * (int)sizeof(float);  // 64 KB
    cudaFuncSetAttribute(window_attn_kernel,
                         cudaFuncAttributeMaxDynamicSharedMemorySize, smem_attn);

    const int WN4 = Dc * Dc / 4;
    const int XN4 = Mrows * Dc / 4;
    const dim3 ggrid(Dc / BN, Mrows / BM);   // (8, 128)

    // Round the four weight matrices to tf32
    const float* Ws[4] = {Wq, Wk, Wv, Wo};
    for (int w = 0; w < 4; w++)
        round_tf32_kernel<<<(WN4 + 255) / 256, 256>>>(
            Ws[w], Wr + (size_t)w * Dc * Dc, WN4);

    // Q projection
    round_tf32_kernel<<<(XN4 + 255) / 256, 256>>>(query, Xr, XN4);
    gemm_tf32_kernel<<<ggrid, 256, SMEM_GEMM>>>(Xr, Wr, bq, Qb);
    // K projection
    round_tf32_kernel<<<(XN4 + 255) / 256, 256>>>(key, Xr, XN4);
    gemm_tf32_kernel<<<ggrid, 256, SMEM_GEMM>>>(
        Xr, Wr + (size_t)1 * Dc * Dc, bk, Kb);
    // V projection
    round_tf32_kernel<<<(XN4 + 255) / 256, 256>>>(value, Xr, XN4);
    gemm_tf32_kernel<<<ggrid, 256, SMEM_GEMM>>>(
        Xr, Wr + (size_t)2 * Dc * Dc, bv, Vb);

    // Windowed attention (writes tf32-rounded output into Xr)
    window_attn_kernel<<<dim3(NWIN, Hc), 128, smem_attn>>>(Qb, Kb, Vb, Xr);

    // Output projection
    gemm_tf32_kernel<<<ggrid, 256, SMEM_GEMM>>>(
        Xr, Wr + (size_t)3 * Dc * Dc, bo, out);

    // Global attention on gathered tokens, project + scatter (overwrites rows)
    global_attn_kernel<<<dim3(Bc, Hc), 32>>>(Qb, Kb, Vb, gidx, GOb);
    global_proj_kernel<<<dim3(Bc * 32, Dc / 256), 256>>>(GOb, Wo, bo, gidx, out);
}

// round 5
// speedup vs baseline: 2.9980x; 1.2482x over previous
#include <cuda_runtime.h>
#include <cstdint>
#include <math.h>

// ---------------------------------------------------------------------------
// Problem constants
// ---------------------------------------------------------------------------
constexpr int Bc = 4;
constexpr int Sc = 4096;
constexpr int Dc = 1024;
constexpr int Hc = 16;
constexpr int HDc = 64;
constexpr int Wc = 128;
constexpr int NWIN = Bc * (Sc / Wc);   // 128 windows
constexpr int Mrows = Bc * Sc;         // 16384

// ---------------------------------------------------------------------------
// Scratch (device globals: allocation-free rule)
// ---------------------------------------------------------------------------
__device__ float g_Q[Mrows * Dc];
__device__ float g_K[Mrows * Dc];
__device__ float g_V[Mrows * Dc];
__device__ __align__(128) float g_Xr[Mrows * Dc];   // tf32-rounded+permuted acts
__device__ __align__(128) float g_Wr[4][Dc * Dc];   // tf32-rounded+permuted weights
__device__ float g_GO[Bc * 32 * Dc];

// ---------------------------------------------------------------------------
// PTX helpers (baseline ISA: cp.async / mma.sync tf32)
// ---------------------------------------------------------------------------
__device__ __forceinline__ uint32_t smem_to_u32(const void* p) {
    uint32_t a;
    asm("{ .reg .u64 t; cvta.to.shared.u64 t, %1; cvt.u32.u64 %0, t; }"
        : "=r"(a) : "l"(p));
    return a;
}
__device__ __forceinline__ void cp_async16(uint32_t dst, const void* src) {
    asm volatile("cp.async.cg.shared.global [%0], [%1], 16;"
                 :: "r"(dst), "l"(src));
}
#define CP_COMMIT() asm volatile("cp.async.commit_group;" ::: "memory")
#define CP_WAIT(n)  asm volatile("cp.async.wait_group %0;" :: "n"(n) : "memory")

__device__ __forceinline__ float tf32f(float x) {
    uint32_t r;
    asm("cvt.rna.tf32.f32 %0, %1;" : "=r"(r) : "f"(x));
    return __uint_as_float(r);
}
__device__ __forceinline__ uint32_t u32(float x) { return __float_as_uint(x); }

#define MMA_TF32(d, a0v, a1v, a2v, a3v, b0v, b1v) \
    asm volatile("mma.sync.aligned.m16n8k8.row.col.f32.tf32.tf32.f32 " \
        "{%0,%1,%2,%3}, {%4,%5,%6,%7}, {%8,%9}, {%0,%1,%2,%3};" \
        : "+f"((d)[0]), "+f"((d)[1]), "+f"((d)[2]), "+f"((d)[3]) \
        : "r"(a0v), "r"(a1v), "r"(a2v), "r"(a3v), "r"(b0v), "r"(b1v))

// permutation within each 8-element k-group: k -> 2*(k&3) + (k>>2)
__device__ __forceinline__ int permc(int j) { return ((j & 3) << 1) | ((j >> 2) & 1); }

// ---------------------------------------------------------------------------
// fp32 -> tf32-rounded fp32 with k-permuted layout (8-element groups)
// thread handles 8 consecutive elements.
// ---------------------------------------------------------------------------
__global__ __launch_bounds__(256) void round_perm_kernel(
    const float* __restrict__ x, float* __restrict__ y, int n8)
{
    int i = blockIdx.x * 256 + threadIdx.x;
    if (i >= n8) return;
    const float4* xp = (const float4*)x;
    float4 v0 = xp[2 * i], v1 = xp[2 * i + 1];
    float4 o0, o1;
    // out[0]=in0 out[1]=in4 out[2]=in1 out[3]=in5 out[4]=in2 out[5]=in6 out[6]=in3 out[7]=in7
    o0.x = tf32f(v0.x); o0.y = tf32f(v1.x); o0.z = tf32f(v0.y); o0.w = tf32f(v1.y);
    o1.x = tf32f(v0.z); o1.y = tf32f(v1.z); o1.z = tf32f(v0.w); o1.w = tf32f(v1.w);
    ((float4*)y)[2 * i] = o0;
    ((float4*)y)[2 * i + 1] = o1;
}

// ---------------------------------------------------------------------------
// tf32 mma GEMM: Y[m,n] = sum_k X[m,k]*Wt[n,k] + bias[n]
// Inputs pre-rounded & k-permuted. BM=BN=128, BK=32, 128 threads, 4 warps
// in 2x2 grid of 64x64 warp tiles. LDS.64 fragment loads, ROWF=40 pad.
// ---------------------------------------------------------------------------
constexpr int GBM = 128, GBN = 128, GBK = 32;
constexpr int ROWF = 40;                        // floats per smem row
constexpr int TILE_B = 128 * ROWF * 4;          // 20480 B per matrix tile
constexpr int STAGE_B = 2 * TILE_B;             // 40960
constexpr int SMEM_GEMM = 2 * STAGE_B;          // 81920
constexpr int NCHUNK = Dc / GBK;                // 32

__global__ __launch_bounds__(128, 2) void gemm_tf32_kernel(
    const float* __restrict__ A, const float* __restrict__ Bm,
    const float* __restrict__ bias, float* __restrict__ Y)
{
    extern __shared__ __align__(128) char smem[];
    const uint32_t sbase = smem_to_u32(smem);
    const int tid = threadIdx.x;
    const int lane = tid & 31;
    const int wid = tid >> 5;
    const int wm = wid >> 1;        // 0..1 -> 64-row slab
    const int wn = wid & 1;         // 0..1 -> 64-col slab
    const int m0 = blockIdx.y * GBM;
    const int n0 = blockIdx.x * GBN;
    const int g = lane >> 2;        // 0..7
    const int t = lane & 3;         // 0..3

    float acc[4][8][4];
#pragma unroll
    for (int mi = 0; mi < 4; mi++)
#pragma unroll
        for (int nt = 0; nt < 8; nt++)
#pragma unroll
            for (int e = 0; e < 4; e++) acc[mi][nt][e] = 0.f;

    auto issue = [&](int c, int s) {
        const int k0 = c * GBK;
        const uint32_t sb = sbase + s * STAGE_B;
#pragma unroll
        for (int i = 0; i < 8; i++) {               // A: 128 rows x 8 chunks
            int idx = tid + i * 128;                // 0..1023
            int r = idx >> 3, ch = idx & 7;
            cp_async16(sb + r * (ROWF * 4) + ch * 16,
                       A + (size_t)(m0 + r) * Dc + k0 + ch * 4);
        }
#pragma unroll
        for (int i = 0; i < 8; i++) {               // B
            int idx = tid + i * 128;
            int r = idx >> 3, ch = idx & 7;
            cp_async16(sb + TILE_B + r * (ROWF * 4) + ch * 16,
                       Bm + (size_t)(n0 + r) * Dc + k0 + ch * 4);
        }
        CP_COMMIT();
    };

    issue(0, 0);
    issue(1, 1);

    for (int c = 0; c < NCHUNK; c++) {
        const int s = c & 1;
        if (c < NCHUNK - 2) { CP_WAIT(1); } else { CP_WAIT(0); }
        __syncthreads();

        const float* As = (const float*)(smem + s * STAGE_B);
        const float* Bs = (const float*)(smem + s * STAGE_B + TILE_B);

#pragma unroll
        for (int ks = 0; ks < 4; ks++) {
            const int kk = ks * 8;
            float2 bf[8];
#pragma unroll
            for (int nt = 0; nt < 8; nt++)
                bf[nt] = *(const float2*)&Bs[(wn * 64 + nt * 8 + g) * ROWF + kk + 2 * t];
#pragma unroll
            for (int mi = 0; mi < 4; mi++) {
                const int mr = wm * 64 + mi * 16 + g;
                float2 a0 = *(const float2*)&As[mr * ROWF + kk + 2 * t];
                float2 a1 = *(const float2*)&As[(mr + 8) * ROWF + kk + 2 * t];
#pragma unroll
                for (int nt = 0; nt < 8; nt++)
                    MMA_TF32(acc[mi][nt], u32(a0.x), u32(a1.x), u32(a0.y), u32(a1.y),
                             u32(bf[nt].x), u32(bf[nt].y));
            }
        }
        __syncthreads();
        if (c + 2 < NCHUNK) issue(c + 2, s);
    }

    // Epilogue: registers -> gmem with fused bias (float2, coalesced)
#pragma unroll
    for (int nt = 0; nt < 8; nt++) {
        const int n = n0 + wn * 64 + nt * 8 + 2 * t;
        const float b0 = bias[n], b1 = bias[n + 1];
#pragma unroll
        for (int mi = 0; mi < 4; mi++) {
            const int r0 = m0 + wm * 64 + mi * 16 + g;
            float2 v0, v1;
            v0.x = acc[mi][nt][0] + b0; v0.y = acc[mi][nt][1] + b1;
            v1.x = acc[mi][nt][2] + b0; v1.y = acc[mi][nt][3] + b1;
            *(float2*)&Y[(size_t)r0 * Dc + n] = v0;
            *(float2*)&Y[(size_t)(r0 + 8) * Dc + n] = v1;
        }
    }
}

// ---------------------------------------------------------------------------
// Windowed attention via tensor cores. grid (NWIN, H), 256 threads (8 warps,
// 16 Q-rows each). Single 128-key block: exact softmax, no online rescale.
// S = Q*K^T in 2-pass split-Q tf32 mma; P through smem; O = P*V tf32 mma.
// Output written tf32-rounded + k-permuted into Xr for the final projection.
// ---------------------------------------------------------------------------
constexpr int QSTR = 72;    // row stride (floats) for Qh/Ql/Ks  [row][d]
constexpr int VSTR = 136;   // row stride for Vs [d][key]
constexpr int PSTR = 136;   // row stride for Ps [row][key]
constexpr int OFF_QH = 0;
constexpr int OFF_QL = OFF_QH + 128 * QSTR;     // 9216
constexpr int OFF_K  = OFF_QL + 128 * QSTR;     // 18432
constexpr int OFF_V  = OFF_K + 128 * QSTR;      // 27648
constexpr int OFF_P  = OFF_V + 64 * VSTR;       // 36352
constexpr int SMEM_ATTN = (OFF_P + 128 * PSTR) * 4;  // 215040 B

__global__ __launch_bounds__(256, 1) void window_attn_mma_kernel(
    const float* __restrict__ Qp, const float* __restrict__ Kp,
    const float* __restrict__ Vp, float* __restrict__ Xr)
{
    extern __shared__ __align__(16) float sm[];
    float* Qh = sm + OFF_QH;
    float* Ql = sm + OFF_QL;
    float* Ks = sm + OFF_K;
    float* Vs = sm + OFF_V;
    float* Ps = sm + OFF_P;

    const int win = blockIdx.x;
    const int h = blockIdx.y;
    const size_t base = (size_t)win * Wc * Dc + h * HDc;
    const int tid = threadIdx.x;

    // Stage Q (hi/lo split), K, V — tf32-rounded, k/key-permuted layouts.
    for (int idx = tid; idx < Wc * HDc; idx += 256) {
        int row = idx >> 6, col = idx & 63;
        int pc = (col & ~7) | permc(col & 7);
        size_t ga = base + (size_t)row * Dc + col;
        float q = Qp[ga];
        float hi = tf32f(q);
        Qh[row * QSTR + pc] = hi;
        Ql[row * QSTR + pc] = tf32f(q - hi);
        Ks[row * QSTR + pc] = tf32f(Kp[ga]);
        int pk = (row & ~7) | permc(row & 7);
        Vs[col * VSTR + pk] = tf32f(Vp[ga]);
    }
    __syncthreads();

    const int w = tid >> 5;
    const int lane = tid & 31;
    const int g = lane >> 2, t = lane & 3;
    const int r0 = w * 16 + g, r1 = r0 + 8;
    const int pc0 = permc(2 * t), pc1 = permc(2 * t + 1);

    // ---- S = Q*K^T (2-pass: Qhi + Qlo) ----
    float sa[16][4];
#pragma unroll
    for (int nt = 0; nt < 16; nt++)
#pragma unroll
        for (int e = 0; e < 4; e++) sa[nt][e] = 0.f;

#pragma unroll
    for (int kt = 0; kt < 8; kt++) {
        const int kk = kt * 8 + 2 * t;
        float2 ah0 = *(const float2*)&Qh[r0 * QSTR + kk];
        float2 ah1 = *(const float2*)&Qh[r1 * QSTR + kk];
        float2 al0 = *(const float2*)&Ql[r0 * QSTR + kk];
        float2 al1 = *(const float2*)&Ql[r1 * QSTR + kk];
#pragma unroll
        for (int nt = 0; nt < 16; nt++) {
            float2 b = *(const float2*)&Ks[(nt * 8 + g) * QSTR + kk];
            MMA_TF32(sa[nt], u32(ah0.x), u32(ah1.x), u32(ah0.y), u32(ah1.y),
                     u32(b.x), u32(b.y));
            MMA_TF32(sa[nt], u32(al0.x), u32(al1.x), u32(al0.y), u32(al1.y),
                     u32(b.x), u32(b.y));
        }
    }

    // ---- softmax (rows r0, r1) ----
    float mx0 = -1e30f, mx1 = -1e30f;
#pragma unroll
    for (int nt = 0; nt < 16; nt++) {
#pragma unroll
        for (int e = 0; e < 4; e++) sa[nt][e] *= 0.125f;
        mx0 = fmaxf(mx0, fmaxf(sa[nt][0], sa[nt][1]));
        mx1 = fmaxf(mx1, fmaxf(sa[nt][2], sa[nt][3]));
    }
    mx0 = fmaxf(mx0, __shfl_xor_sync(0xffffffffu, mx0, 1));
    mx0 = fmaxf(mx0, __shfl_xor_sync(0xffffffffu, mx0, 2));
    mx1 = fmaxf(mx1, __shfl_xor_sync(0xffffffffu, mx1, 1));
    mx1 = fmaxf(mx1, __shfl_xor_sync(0xffffffffu, mx1, 2));

    float l0 = 0.f, l1 = 0.f;
#pragma unroll
    for (int nt = 0; nt < 16; nt++) {
        float p00 = __expf(sa[nt][0] - mx0);
        float p01 = __expf(sa[nt][1] - mx0);
        float p10 = __expf(sa[nt][2] - mx1);
        float p11 = __expf(sa[nt][3] - mx1);
        l0 += p00 + p01;
        l1 += p10 + p11;
        Ps[r0 * PSTR + nt * 8 + pc0] = tf32f(p00);
        Ps[r0 * PSTR + nt * 8 + pc1] = tf32f(p01);
        Ps[r1 * PSTR + nt * 8 + pc0] = tf32f(p10);
        Ps[r1 * PSTR + nt * 8 + pc1] = tf32f(p11);
    }
    l0 += __shfl_xor_sync(0xffffffffu, l0, 1);
    l0 += __shfl_xor_sync(0xffffffffu, l0, 2);
    l1 += __shfl_xor_sync(0xffffffffu, l1, 1);
    l1 += __shfl_xor_sync(0xffffffffu, l1, 2);
    __syncwarp();

    // ---- O = P*V ----
    float oa[8][4];
#pragma unroll
    for (int nt = 0; nt < 8; nt++)
#pragma unroll
        for (int e = 0; e < 4; e++) oa[nt][e] = 0.f;

#pragma unroll
    for (int kt = 0; kt < 16; kt++) {
        const int kk = kt * 8 + 2 * t;
        float2 a0 = *(const float2*)&Ps[r0 * PSTR + kk];
        float2 a1 = *(const float2*)&Ps[r1 * PSTR + kk];
#pragma unroll
        for (int nt = 0; nt < 8; nt++) {
            float2 b = *(const float2*)&Vs[(nt * 8 + g) * VSTR + kk];
            MMA_TF32(oa[nt], u32(a0.x), u32(a1.x), u32(a0.y), u32(a1.y),
                     u32(b.x), u32(b.y));
        }
    }

    const float inv0 = 1.f / l0, inv1 = 1.f / l1;
    float* o0p = Xr + (size_t)(win * Wc + r0) * Dc + h * HDc;
    float* o1p = Xr + (size_t)(win * Wc + r1) * Dc + h * HDc;
#pragma unroll
    for (int nt = 0; nt < 8; nt++) {
        o0p[nt * 8 + pc0] = tf32f(oa[nt][0] * inv0);
        o0p[nt * 8 + pc1] = tf32f(oa[nt][1] * inv0);
        o1p[nt * 8 + pc0] = tf32f(oa[nt][2] * inv1);
        o1p[nt * 8 + pc1] = tf32f(oa[nt][3] * inv1);
    }
}

// ---------------------------------------------------------------------------
// Global attention over 32 gathered tokens (fp32 exact). grid (B, H), 32 thr.
// ---------------------------------------------------------------------------
__global__ __launch_bounds__(32) void global_attn_kernel(
    const float* __restrict__ Qp, const float* __restrict__ Kp,
    const float* __restrict__ Vp, const int* __restrict__ gidx,
    float* __restrict__ GO)
{
    __shared__ __align__(16) float Ks[32 * 64];
    __shared__ __align__(16) float Vs[32 * 64];
    __shared__ int sidx[32];

    const int b = blockIdx.x, h = blockIdx.y, tid = threadIdx.x;
    sidx[tid] = gidx[tid];
    __syncthreads();

    for (int idx = tid; idx < 32 * 64; idx += 32) {
        int rr = idx >> 6, c = idx & 63;
        size_t gg = ((size_t)b * Sc + sidx[rr]) * Dc + h * HDc + c;
        Ks[idx] = Kp[gg];
        Vs[idx] = Vp[gg];
    }
    __syncthreads();

    const int i = tid;
    size_t qoff = ((size_t)b * Sc + sidx[i]) * Dc + h * HDc;
    float q[64];
#pragma unroll
    for (int d = 0; d < 64; d++) q[d] = Qp[qoff + d];

    float s[32];
    float mx = -1e30f;
    for (int j = 0; j < 32; j++) {
        float a = 0.f;
#pragma unroll
        for (int d = 0; d < 64; d++) a += q[d] * Ks[j * 64 + d];
        a *= 0.125f;
        s[j] = a;
        mx = fmaxf(mx, a);
    }
    float l = 0.f;
    for (int j = 0; j < 32; j++) { s[j] = __expf(s[j] - mx); l += s[j]; }

    float acc[64];
#pragma unroll
    for (int d = 0; d < 64; d++) acc[d] = 0.f;
    for (int j = 0; j < 32; j++) {
        float p = s[j];
#pragma unroll
        for (int d = 0; d < 64; d++) acc[d] += p * Vs[j * 64 + d];
    }
    float inv = 1.f / l;
    float* o = GO + ((size_t)(b * 32 + i)) * Dc + h * HDc;
#pragma unroll
    for (int d = 0; d < 64; d++) o[d] = acc[d] * inv;
}

// ---------------------------------------------------------------------------
// Project 128 global rows with Wo (fp32 exact), scatter into Y.
// ---------------------------------------------------------------------------
__global__ __launch_bounds__(256) void global_proj_kernel(
    const float* __restrict__ GO, const float* __restrict__ Wo,
    const float* __restrict__ bo, const int* __restrict__ gidx,
    float* __restrict__ Y)
{
    __shared__ __align__(16) float xr[Dc];
    const int row = blockIdx.x;
    const int nb = blockIdx.y;
    const int tid = threadIdx.x;

    for (int i = tid; i < Dc; i += 256) xr[i] = GO[(size_t)row * Dc + i];
    __syncthreads();

    const int n = nb * 256 + tid;
    const float4* wr = (const float4*)(Wo + (size_t)n * Dc);
    const float4* x4 = (const float4*)xr;
    float s0 = 0.f, s1 = 0.f, s2 = 0.f, s3 = 0.f;
#pragma unroll 8
    for (int k = 0; k < Dc / 4; k++) {
        float4 w = wr[k];
        float4 x = x4[k];
        s0 += w.x * x.x; s1 += w.y * x.y; s2 += w.z * x.z; s3 += w.w * x.w;
    }
    float sum = s0 + s1 + s2 + s3 + bo[n];

    const int b = row >> 5, i = row & 31;
    const int tok = gidx[i];
    Y[((size_t)b * Sc + tok) * Dc + n] = sum;
}

// ---------------------------------------------------------------------------
extern "C" void kernel_launch(void* const* d_in, const int* in_sizes, int n_in,
                              void* d_out, int out_size)
{
    const float* query = (const float*)d_in[0];
    const float* key   = (const float*)d_in[1];
    const float* value = (const float*)d_in[2];
    const float* Wq = (const float*)d_in[3];
    const float* bq = (const float*)d_in[4];
    const float* Wk = (const float*)d_in[5];
    const float* bk = (const float*)d_in[6];
    const float* Wv = (const float*)d_in[7];
    const float* bv = (const float*)d_in[8];
    const float* Wo = (const float*)d_in[9];
    const float* bo = (const float*)d_in[10];
    const int* gidx = (const int*)d_in[11];
    float* out = (float*)d_out;

    float *Qb, *Kb, *Vb, *Xr, *Wr, *GOb;
    cudaGetSymbolAddress((void**)&Qb, g_Q);
    cudaGetSymbolAddress((void**)&Kb, g_K);
    cudaGetSymbolAddress((void**)&Vb, g_V);
    cudaGetSymbolAddress((void**)&Xr, g_Xr);
    cudaGetSymbolAddress((void**)&Wr, g_Wr);
    cudaGetSymbolAddress((void**)&GOb, g_GO);

    cudaFuncSetAttribute(gemm_tf32_kernel,
                         cudaFuncAttributeMaxDynamicSharedMemorySize, SMEM_GEMM);
    cudaFuncSetAttribute(window_attn_mma_kernel,
                         cudaFuncAttributeMaxDynamicSharedMemorySize, SMEM_ATTN);

    const int WN8 = Dc * Dc / 8;
    const int XN8 = Mrows * Dc / 8;
    const dim3 ggrid(Dc / GBN, Mrows / GBM);   // (8, 128)

    // Round + permute the four weight matrices
    const float* Ws[4] = {Wq, Wk, Wv, Wo};
    for (int w = 0; w < 4; w++)
        round_perm_kernel<<<(WN8 + 255) / 256, 256>>>(
            Ws[w], Wr + (size_t)w * Dc * Dc, WN8);

    // Q projection
    round_perm_kernel<<<(XN8 + 255) / 256, 256>>>(query, Xr, XN8);
    gemm_tf32_kernel<<<ggrid, 128, SMEM_GEMM>>>(Xr, Wr, bq, Qb);
    // K projection
    round_perm_kernel<<<(XN8 + 255) / 256, 256>>>(key, Xr, XN8);
    gemm_tf32_kernel<<<ggrid, 128, SMEM_GEMM>>>(
        Xr, Wr + (size_t)1 * Dc * Dc, bk, Kb);
    // V projection
    round_perm_kernel<<<(XN8 + 255) / 256, 256>>>(value, Xr, XN8);
    gemm_tf32_kernel<<<ggrid, 128, SMEM_GEMM>>>(
        Xr, Wr + (size_t)2 * Dc * Dc, bv, Vb);

    // Windowed attention (tensor cores; writes tf32+permuted output into Xr)
    window_attn_mma_kernel<<<dim3(NWIN, Hc), 256, SMEM_ATTN>>>(Qb, Kb, Vb, Xr);

    // Output projection
    gemm_tf32_kernel<<<ggrid, 128, SMEM_GEMM>>>(
        Xr, Wr + (size_t)3 * Dc * Dc, bo, out);

    // Global attention on gathered tokens, project + scatter (overwrites rows)
    global_attn_kernel<<<dim3(Bc, Hc), 32>>>(Qb, Kb, Vb, gidx, GOb);
    global_proj_kernel<<<dim3(Bc * 32, Dc / 256), 256>>>(GOb, Wo, bo, gidx, out);
}